// round 15
// baseline (speedup 1.0000x reference)
#include <cuda_runtime.h>
#include <cstdint>

#define BB 256
#define SS 2048
#define FF 64
#define KD 320   // ORDER * FF

// ---------------------------------------------------------------------------
// f32x2 helpers
// ---------------------------------------------------------------------------
__device__ __forceinline__ uint64_t pack2(float a, float b) {
    uint64_t r; asm("mov.b64 %0,{%1,%2};" : "=l"(r) : "f"(a), "f"(b)); return r;
}
__device__ __forceinline__ void fma2(uint64_t& acc, uint64_t a, uint64_t b) {
    asm("fma.rn.f32x2 %0, %1, %2, %0;" : "+l"(acc) : "l"(a), "l"(b));
}
__device__ __forceinline__ uint64_t add2(uint64_t a, uint64_t b) {
    uint64_t r; asm("add.rn.f32x2 %0, %1, %2;" : "=l"(r) : "l"(a), "l"(b));
    return r;
}
__device__ __forceinline__ float hadd2(uint64_t v) {
    float lo, hi; asm("mov.b64 {%0,%1}, %2;" : "=f"(lo), "=f"(hi) : "l"(v));
    return lo + hi;
}
__device__ __forceinline__ uint64_t shfl_xor64(uint64_t v, int d) {
    uint32_t lo = (uint32_t)v, hi = (uint32_t)(v >> 32);
    lo = __shfl_xor_sync(0xffffffffu, lo, d);
    hi = __shfl_xor_sync(0xffffffffu, hi, d);
    return ((uint64_t)hi << 32) | lo;
}

// ---------------------------------------------------------------------------
// Fused kernel, TIME-MULTIPLEXED: grid = 128 CTAs of 128 threads — exactly
// ONE CTA per SM (single wave, no co-resident CTA contention). Each CTA
// processes batches 2*blockIdx.x and 2*blockIdx.x+1 SEQUENTIALLY, reusing
// its register-resident W across both.
//
// Per batch: fused mean prologue (vectorized), then the R13 recurrence:
// thread = (fg, q), fg = 4 contiguous output features, q = K-octant; W
// register-resident (80 f32x2); window register-cached (5 circular 8-float
// slices), newest frame re-read from smem each step; software pipeline (64
// partial FFMA2 pre-barrier, interleaved between shfl levels); multi-value
// 4-SHFL reduction; lanes q<4 write win (critical STS), q>=4 write output.
// ---------------------------------------------------------------------------
__global__ __launch_bounds__(128, 1) void var_kernel(
    const float* __restrict__ x, const int* __restrict__ mask,
    const float* __restrict__ W, const float* __restrict__ bias,
    float* __restrict__ out)
{
    int tid = threadIdx.x;
    int fg  = tid >> 3;     // 0..15 feature group
    int q   = tid & 7;      // 0..7  K-octant
    int f0  = fg << 2;
    int ko  = q << 3;
    int v   = ((q & 1) << 1) | ((q >> 1) & 1);   // owned feature after reduce
    int fv  = f0 + v;

    __shared__ __align__(16) float win[5][FF];   // circular frame buffer
    __shared__ float smean[FF];
    __shared__ float ssum[8][FF];
    __shared__ float scnt[8][FF];

    // W registers (loaded ONCE, reused for both batches): w[g][row j][pair]
    uint64_t w[4][5][4];
    #pragma unroll
    for (int g = 0; g < 4; g++) {
        #pragma unroll
        for (int j = 0; j < 5; j++) {
            const float4* p4 = (const float4*)(W + (size_t)(f0 + g) * KD + j * FF + ko);
            float4 a = p4[0], c = p4[1];
            w[g][j][0] = pack2(a.x, a.y); w[g][j][1] = pack2(a.z, a.w);
            w[g][j][2] = pack2(c.x, c.y); w[g][j][3] = pack2(c.z, c.w);
        }
    }
    float bs = bias[fv];

    // Partial-FMA chunk over surviving slot s for phase P (16 FFMA2).
    #define PCHUNK(P, s)                                                       \
        if ((s) != (P)) {                                                      \
            const int jp = ((s) - (P) - 1 + 5) % 5;                            \
            _Pragma("unroll")                                                  \
            for (int o = 0; o < 4; o++) {                                      \
                fma2(np0, w[0][jp][o], wr[s][o]);                              \
                fma2(np1, w[1][jp][o], wr[s][o]);                              \
                fma2(np2, w[2][jp][o], wr[s][o]);                              \
                fma2(np3, w[3][jp][o], wr[s][o]);                              \
            }                                                                  \
        }

    // One recurrence step at static phase P. Advances t by 1. (R13 schedule)
    #define STEP(P)                                                            \
    do {                                                                       \
        {                                                                      \
            const float4* nf = (const float4*)(&win[(P + 4) % 5][ko]);         \
            float4 a = nf[0], c = nf[1];                                       \
            wr[(P + 4) % 5][0] = pack2(a.x, a.y);                              \
            wr[(P + 4) % 5][1] = pack2(a.z, a.w);                              \
            wr[(P + 4) % 5][2] = pack2(c.x, c.y);                              \
            wr[(P + 4) % 5][3] = pack2(c.z, c.w);                              \
        }                                                                      \
        int tc = (t + 1 < SS) ? (t + 1) : (SS - 1);                            \
        float xv_n = xs[(size_t)tc * FF];                                      \
        int   mv_n = ms[(size_t)tc * FF];                                      \
        uint64_t ca0 = part0, cb0 = 0, ca1 = part1, cb1 = 0;                   \
        uint64_t ca2 = part2, cb2 = 0, ca3 = part3, cb3 = 0;                   \
        {                                                                      \
            const int sN = (P + 4) % 5;                                        \
            fma2(ca0, w[0][4][0], wr[sN][0]); fma2(cb0, w[0][4][1], wr[sN][1]);\
            fma2(ca0, w[0][4][2], wr[sN][2]); fma2(cb0, w[0][4][3], wr[sN][3]);\
            fma2(ca1, w[1][4][0], wr[sN][0]); fma2(cb1, w[1][4][1], wr[sN][1]);\
            fma2(ca1, w[1][4][2], wr[sN][2]); fma2(cb1, w[1][4][3], wr[sN][3]);\
            fma2(ca2, w[2][4][0], wr[sN][0]); fma2(cb2, w[2][4][1], wr[sN][1]);\
            fma2(ca2, w[2][4][2], wr[sN][2]); fma2(cb2, w[2][4][3], wr[sN][3]);\
            fma2(ca3, w[3][4][0], wr[sN][0]); fma2(cb3, w[3][4][1], wr[sN][1]);\
            fma2(ca3, w[3][4][2], wr[sN][2]); fma2(cb3, w[3][4][3], wr[sN][3]);\
        }                                                                      \
        float r0 = hadd2(add2(ca0, cb0)), r1 = hadd2(add2(ca1, cb1));          \
        float r2 = hadd2(add2(ca2, cb2)), r3 = hadd2(add2(ca3, cb3));          \
        uint64_t np0 = 0, np1 = 0, np2 = 0, np3 = 0;                           \
        uint64_t snd1 = (q & 1) ? pack2(r0, r1) : pack2(r2, r3);               \
        uint64_t kp1  = (q & 1) ? pack2(r2, r3) : pack2(r0, r1);               \
        uint64_t rc1  = shfl_xor64(snd1, 1);                                   \
        PCHUNK(P, 0); PCHUNK(P, 1);                                            \
        uint64_t v2 = add2(kp1, rc1);                                          \
        float va, vb;                                                          \
        asm("mov.b64 {%0,%1}, %2;" : "=f"(va), "=f"(vb) : "l"(v2));            \
        float kp2  = (q & 2) ? vb : va;                                        \
        float snd2 = (q & 2) ? va : vb;                                        \
        float rc2  = __shfl_xor_sync(0xffffffffu, snd2, 2);                    \
        PCHUNK(P, 2); PCHUNK(P, 3);                                            \
        float r4 = kp2 + rc2;                                                  \
        float rc3 = __shfl_xor_sync(0xffffffffu, r4, 4);                       \
        PCHUNK(P, 4);                                                          \
        float rsum = r4 + rc3;                                                 \
        float nv = mv ? xv : (rsum + bs);                                      \
        if (q < 4) {                                                           \
            win[(P)][fv] = nv;            /* pre-barrier critical STS */       \
        } else {                                                               \
            os[(size_t)t * FF] = nv;      /* fire-and-forget STG */            \
        }                                                                      \
        xv = xv_n; mv = mv_n;                                                  \
        part0 = np0; part1 = np1; part2 = np2; part3 = np3;                    \
        __syncthreads();                                                       \
        t++;                                                                   \
    } while (0)

    // ======================= two batches, sequential =======================
    for (int half = 0; half < 2; half++) {
        int b = blockIdx.x * 2 + half;

        // ---- fused mean prologue: thread = (chunk c=tid>>4, quad=tid&15) --
        {
            int quad = tid & 15;
            int c    = tid >> 4;             // 8 chunks of 256 steps
            const float4* xb4 = (const float4*)(x    + (size_t)b * SS * FF);
            const int4*   mb4 = (const int4*)  (mask + (size_t)b * SS * FF);
            float4 sum = {0.f, 0.f, 0.f, 0.f};
            float4 cnt = {0.f, 0.f, 0.f, 0.f};
            int base = c * 256;
            #pragma unroll 4
            for (int s = 0; s < 256; s++) {
                int idx = (base + s) * 16 + quad;
                float4 xv4 = xb4[idx];
                int4   m4  = mb4[idx];
                if (m4.x) { sum.x += xv4.x; cnt.x += 1.f; }
                if (m4.y) { sum.y += xv4.y; cnt.y += 1.f; }
                if (m4.z) { sum.z += xv4.z; cnt.z += 1.f; }
                if (m4.w) { sum.w += xv4.w; cnt.w += 1.f; }
            }
            ssum[c][quad * 4 + 0] = sum.x; ssum[c][quad * 4 + 1] = sum.y;
            ssum[c][quad * 4 + 2] = sum.z; ssum[c][quad * 4 + 3] = sum.w;
            scnt[c][quad * 4 + 0] = cnt.x; scnt[c][quad * 4 + 1] = cnt.y;
            scnt[c][quad * 4 + 2] = cnt.z; scnt[c][quad * 4 + 3] = cnt.w;
            __syncthreads();
            if (tid < FF) {
                float s = 0.f, n = 0.f;
                #pragma unroll
                for (int k = 0; k < 8; k++) { s += ssum[k][tid]; n += scnt[k][tid]; }
                smean[tid] = s / (n + 1e-8f);
            }
            __syncthreads();
        }

        // smem window init: per-feature means
        for (int i = tid; i < 5 * FF; i += 128)
            (&win[0][0])[i] = smean[i & 63];

        // register window cache: all 5 slots = mean slice
        uint64_t wr[5][4];
        {
            const float4* mp = (const float4*)(&smean[ko]);
            float4 a = mp[0], c = mp[1];
            #pragma unroll
            for (int j = 0; j < 5; j++) {
                wr[j][0] = pack2(a.x, a.y); wr[j][1] = pack2(a.z, a.w);
                wr[j][2] = pack2(c.x, c.y); wr[j][3] = pack2(c.z, c.w);
            }
        }

        const float* xs = x    + (size_t)b * SS * FF + fv;
        const int*   ms = mask + (size_t)b * SS * FF + fv;
        float*       os = out  + (size_t)b * SS * FF + fv;

        // Prefetch step 0 (all lanes)
        float xv = xs[0];
        int   mv = ms[0];

        // Bootstrap partial for phase 0: slots s=0..3 carry rows 0..3.
        uint64_t part0 = 0, part1 = 0, part2 = 0, part3 = 0;
        #pragma unroll
        for (int s = 0; s < 4; s++) {
            #pragma unroll
            for (int o = 0; o < 4; o++) {
                fma2(part0, w[0][s][o], wr[s][o]);
                fma2(part1, w[1][s][o], wr[s][o]);
                fma2(part2, w[2][s][o], wr[s][o]);
                fma2(part3, w[3][s][o], wr[s][o]);
            }
        }

        __syncthreads();

        int t = 0;
        // 409 * 5 = 2045 steps
        for (int it = 0; it < 409; it++) {
            STEP(0); STEP(1); STEP(2); STEP(3); STEP(4);
        }
        // epilogue: t = 2045..2047 (phases 0,1,2 since 2045 % 5 == 0)
        STEP(0); STEP(1); STEP(2);
        // last STEP ends with __syncthreads -> smem safe to reuse next half
    }

    #undef STEP
    #undef PCHUNK
}

// ---------------------------------------------------------------------------
extern "C" void kernel_launch(void* const* d_in, const int* in_sizes, int n_in,
                              void* d_out, int out_size) {
    const float* x    = (const float*)d_in[0];
    const int*   mask = (const int*)  d_in[1];
    const float* W    = (const float*)d_in[2];
    const float* bias = (const float*)d_in[3];
    float*       out  = (float*)d_out;

    var_kernel<<<BB / 2, 128>>>(x, mask, W, bias, out);
}

// round 16
// speedup vs baseline: 2.2345x; 2.2345x over previous
#include <cuda_runtime.h>
#include <cstdint>

#define BB 256
#define SS 2048
#define FF 64
#define KD 320   // ORDER * FF

// ---------------------------------------------------------------------------
// f32x2 helpers
// ---------------------------------------------------------------------------
__device__ __forceinline__ uint64_t pack2(float a, float b) {
    uint64_t r; asm("mov.b64 %0,{%1,%2};" : "=l"(r) : "f"(a), "f"(b)); return r;
}
__device__ __forceinline__ void fma2(uint64_t& acc, uint64_t a, uint64_t b) {
    asm("fma.rn.f32x2 %0, %1, %2, %0;" : "+l"(acc) : "l"(a), "l"(b));
}
__device__ __forceinline__ uint64_t add2(uint64_t a, uint64_t b) {
    uint64_t r; asm("add.rn.f32x2 %0, %1, %2;" : "=l"(r) : "l"(a), "l"(b));
    return r;
}
__device__ __forceinline__ float hadd2(uint64_t v) {
    float lo, hi; asm("mov.b64 {%0,%1}, %2;" : "=f"(lo), "=f"(hi) : "l"(v));
    return lo + hi;
}
__device__ __forceinline__ uint64_t shfl_xor64(uint64_t v, int d) {
    uint32_t lo = (uint32_t)v, hi = (uint32_t)(v >> 32);
    lo = __shfl_xor_sync(0xffffffffu, lo, d);
    hi = __shfl_xor_sync(0xffffffffu, hi, d);
    return ((uint64_t)hi << 32) | lo;
}

// ---------------------------------------------------------------------------
// Fused kernel. One CTA (128 threads) per batch, 256 CTAs, 2 CTAs/SM.
// (R13 structure — empirically best — plus L2 prefetch of the x/mask stream
// 8 steps ahead so the per-step depth-1 LDG hits L2 instead of DRAM.)
//
// PROLOGUE (per-CTA): this batch's per-feature observed mean.
//
// RECURRENCE: thread = (fg, q): fg = 4 contiguous output features,
// q = K-octant. W register-resident (80 f32x2/thread); window register-
// cached as 5 circular 8-float slices; only the newest frame re-read from
// smem each step. Software pipeline: at phase P the refreshed slot
// sN=(P+4)%5 carries W-row 4; the 64 partial FFMA2 for t+1 are interleaved
// between the reduction's shfl levels. Multi-value 4-SHFL reduction: lane q
// ends with the full sum of feature v(q)=2*(q&1)+((q>>1)&1); lanes q<4
// write win (critical STS), lanes q>=4 write the output (STG).
// ---------------------------------------------------------------------------
__global__ __launch_bounds__(128, 2) void var_kernel(
    const float* __restrict__ x, const int* __restrict__ mask,
    const float* __restrict__ W, const float* __restrict__ bias,
    float* __restrict__ out)
{
    int tid = threadIdx.x;
    int b   = blockIdx.x;
    int fg  = tid >> 3;     // 0..15 feature group
    int q   = tid & 7;      // 0..7  K-octant
    int f0  = fg << 2;
    int ko  = q << 3;
    int v   = ((q & 1) << 1) | ((q >> 1) & 1);   // owned feature after reduce
    int fv  = f0 + v;

    __shared__ __align__(16) float win[5][FF];   // circular frame buffer
    __shared__ float smean[FF];
    __shared__ float ssum[8][FF];
    __shared__ float scnt[8][FF];

    // ---- fused mean prologue: thread = (chunk c=tid>>4, quad=tid&15) ----
    {
        int quad = tid & 15;
        int c    = tid >> 4;             // 8 chunks of 256 steps
        const float4* xb4 = (const float4*)(x    + (size_t)b * SS * FF);
        const int4*   mb4 = (const int4*)  (mask + (size_t)b * SS * FF);
        float4 sum = {0.f, 0.f, 0.f, 0.f};
        float4 cnt = {0.f, 0.f, 0.f, 0.f};
        int base = c * 256;
        #pragma unroll 4
        for (int s = 0; s < 256; s++) {
            int idx = (base + s) * 16 + quad;
            float4 xv4 = xb4[idx];
            int4   m4  = mb4[idx];
            if (m4.x) { sum.x += xv4.x; cnt.x += 1.f; }
            if (m4.y) { sum.y += xv4.y; cnt.y += 1.f; }
            if (m4.z) { sum.z += xv4.z; cnt.z += 1.f; }
            if (m4.w) { sum.w += xv4.w; cnt.w += 1.f; }
        }
        ssum[c][quad * 4 + 0] = sum.x; ssum[c][quad * 4 + 1] = sum.y;
        ssum[c][quad * 4 + 2] = sum.z; ssum[c][quad * 4 + 3] = sum.w;
        scnt[c][quad * 4 + 0] = cnt.x; scnt[c][quad * 4 + 1] = cnt.y;
        scnt[c][quad * 4 + 2] = cnt.z; scnt[c][quad * 4 + 3] = cnt.w;
        __syncthreads();
        if (tid < FF) {
            float s = 0.f, n = 0.f;
            #pragma unroll
            for (int k = 0; k < 8; k++) { s += ssum[k][tid]; n += scnt[k][tid]; }
            smean[tid] = s / (n + 1e-8f);
        }
        __syncthreads();
    }

    // W registers: w[g][frame-row j][pair]
    uint64_t w[4][5][4];
    #pragma unroll
    for (int g = 0; g < 4; g++) {
        #pragma unroll
        for (int j = 0; j < 5; j++) {
            const float4* p4 = (const float4*)(W + (size_t)(f0 + g) * KD + j * FF + ko);
            float4 a = p4[0], c = p4[1];
            w[g][j][0] = pack2(a.x, a.y); w[g][j][1] = pack2(a.z, a.w);
            w[g][j][2] = pack2(c.x, c.y); w[g][j][3] = pack2(c.z, c.w);
        }
    }
    float bs = bias[fv];

    // smem window init: per-feature means
    for (int i = tid; i < 5 * FF; i += 128)
        (&win[0][0])[i] = smean[i & 63];

    // register window cache: all 5 slots = mean slice
    uint64_t wr[5][4];
    {
        const float4* mp = (const float4*)(&smean[ko]);
        float4 a = mp[0], c = mp[1];
        #pragma unroll
        for (int j = 0; j < 5; j++) {
            wr[j][0] = pack2(a.x, a.y); wr[j][1] = pack2(a.z, a.w);
            wr[j][2] = pack2(c.x, c.y); wr[j][3] = pack2(c.z, c.w);
        }
    }

    const float* xs = x    + (size_t)b * SS * FF + fv;   // scalar owner stream
    const int*   ms = mask + (size_t)b * SS * FF + fv;
    float*       os = out  + (size_t)b * SS * FF + fv;

    // Prefetch step 0 (all lanes)
    float xv = xs[0];
    int   mv = ms[0];

    // Bootstrap partial for phase 0: slots s=0..3 carry rows 0..3.
    uint64_t part0 = 0, part1 = 0, part2 = 0, part3 = 0;
    #pragma unroll
    for (int s = 0; s < 4; s++) {
        #pragma unroll
        for (int o = 0; o < 4; o++) {
            fma2(part0, w[0][s][o], wr[s][o]);
            fma2(part1, w[1][s][o], wr[s][o]);
            fma2(part2, w[2][s][o], wr[s][o]);
            fma2(part3, w[3][s][o], wr[s][o]);
        }
    }

    __syncthreads();

    int t = 0;

    // Partial-FMA chunk over surviving slot s for phase P (16 FFMA2).
    #define PCHUNK(P, s)                                                       \
        if ((s) != (P)) {                                                      \
            const int jp = ((s) - (P) - 1 + 5) % 5;                            \
            _Pragma("unroll")                                                  \
            for (int o = 0; o < 4; o++) {                                      \
                fma2(np0, w[0][jp][o], wr[s][o]);                              \
                fma2(np1, w[1][jp][o], wr[s][o]);                              \
                fma2(np2, w[2][jp][o], wr[s][o]);                              \
                fma2(np3, w[3][jp][o], wr[s][o]);                              \
            }                                                                  \
        }

    // One recurrence step at static phase P. Advances t by 1.
    #define STEP(P)                                                            \
    do {                                                                       \
        /* L2 prefetch: pull the t+8 x/mask lines into L2 so the depth-1   */  \
        /* LDG below becomes an L2 hit (~250cyc) instead of DRAM (~577).   */  \
        {                                                                      \
            int tp = (t + 8 < SS) ? (t + 8) : (SS - 1);                        \
            asm volatile("prefetch.global.L2 [%0];"                            \
                         :: "l"(xs + (size_t)tp * FF));                        \
            asm volatile("prefetch.global.L2 [%0];"                            \
                         :: "l"(ms + (size_t)tp * FF));                        \
        }                                                                      \
        /* critical path: refresh slot sN=(P+4)%5 (always W-row 4) */          \
        {                                                                      \
            const float4* nf = (const float4*)(&win[(P + 4) % 5][ko]);         \
            float4 a = nf[0], c = nf[1];                                       \
            wr[(P + 4) % 5][0] = pack2(a.x, a.y);                              \
            wr[(P + 4) % 5][1] = pack2(a.z, a.w);                              \
            wr[(P + 4) % 5][2] = pack2(c.x, c.y);                              \
            wr[(P + 4) % 5][3] = pack2(c.z, c.w);                              \
        }                                                                      \
        /* prefetch next x/mask (clamped index, all lanes, independent) */     \
        int tc = (t + 1 < SS) ? (t + 1) : (SS - 1);                            \
        float xv_n = xs[(size_t)tc * FF];                                      \
        int   mv_n = ms[(size_t)tc * FF];                                      \
        /* row-4 FMAs as two 2-deep chains + add */                            \
        uint64_t ca0 = part0, cb0 = 0, ca1 = part1, cb1 = 0;                   \
        uint64_t ca2 = part2, cb2 = 0, ca3 = part3, cb3 = 0;                   \
        {                                                                      \
            const int sN = (P + 4) % 5;                                        \
            fma2(ca0, w[0][4][0], wr[sN][0]); fma2(cb0, w[0][4][1], wr[sN][1]);\
            fma2(ca0, w[0][4][2], wr[sN][2]); fma2(cb0, w[0][4][3], wr[sN][3]);\
            fma2(ca1, w[1][4][0], wr[sN][0]); fma2(cb1, w[1][4][1], wr[sN][1]);\
            fma2(ca1, w[1][4][2], wr[sN][2]); fma2(cb1, w[1][4][3], wr[sN][3]);\
            fma2(ca2, w[2][4][0], wr[sN][0]); fma2(cb2, w[2][4][1], wr[sN][1]);\
            fma2(ca2, w[2][4][2], wr[sN][2]); fma2(cb2, w[2][4][3], wr[sN][3]);\
            fma2(ca3, w[3][4][0], wr[sN][0]); fma2(cb3, w[3][4][1], wr[sN][1]);\
            fma2(ca3, w[3][4][2], wr[sN][2]); fma2(cb3, w[3][4][3], wr[sN][3]);\
        }                                                                      \
        float r0 = hadd2(add2(ca0, cb0)), r1 = hadd2(add2(ca1, cb1));          \
        float r2 = hadd2(add2(ca2, cb2)), r3 = hadd2(add2(ca3, cb3));          \
        /* multi-value reduction, partials interleaved (R8/R13 placement) */   \
        uint64_t np0 = 0, np1 = 0, np2 = 0, np3 = 0;                           \
        uint64_t snd1 = (q & 1) ? pack2(r0, r1) : pack2(r2, r3);               \
        uint64_t kp1  = (q & 1) ? pack2(r2, r3) : pack2(r0, r1);               \
        uint64_t rc1  = shfl_xor64(snd1, 1);                                   \
        PCHUNK(P, 0); PCHUNK(P, 1);                                            \
        uint64_t v2 = add2(kp1, rc1);                                          \
        float va, vb;                                                          \
        asm("mov.b64 {%0,%1}, %2;" : "=f"(va), "=f"(vb) : "l"(v2));            \
        float kp2  = (q & 2) ? vb : va;                                        \
        float snd2 = (q & 2) ? va : vb;                                        \
        float rc2  = __shfl_xor_sync(0xffffffffu, snd2, 2);                    \
        PCHUNK(P, 2); PCHUNK(P, 3);                                            \
        float r4 = kp2 + rc2;                                                  \
        float rc3 = __shfl_xor_sync(0xffffffffu, r4, 4);                       \
        PCHUNK(P, 4);                                                          \
        float rsum = r4 + rc3;                                                 \
        float nv = mv ? xv : (rsum + bs);                                      \
        if (q < 4) {                                                           \
            win[(P)][fv] = nv;            /* pre-barrier critical STS */       \
        } else {                                                               \
            os[(size_t)t * FF] = nv;      /* fire-and-forget STG */            \
        }                                                                      \
        xv = xv_n; mv = mv_n;                                                  \
        part0 = np0; part1 = np1; part2 = np2; part3 = np3;                    \
        __syncthreads();                                                       \
        t++;                                                                   \
    } while (0)

    // 409 * 5 = 2045 steps
    for (int it = 0; it < 409; it++) {
        STEP(0); STEP(1); STEP(2); STEP(3); STEP(4);
    }
    // epilogue: t = 2045, 2046, 2047 (phases 0,1,2 since 2045 % 5 == 0)
    STEP(0); STEP(1); STEP(2);

    #undef STEP
    #undef PCHUNK
}

// ---------------------------------------------------------------------------
extern "C" void kernel_launch(void* const* d_in, const int* in_sizes, int n_in,
                              void* d_out, int out_size) {
    const float* x    = (const float*)d_in[0];
    const int*   mask = (const int*)  d_in[1];
    const float* W    = (const float*)d_in[2];
    const float* bias = (const float*)d_in[3];
    float*       out  = (float*)d_out;

    var_kernel<<<BB, 128>>>(x, mask, W, bias, out);
}